// round 14
// baseline (speedup 1.0000x reference)
#include <cuda_runtime.h>

// ---------------------------------------------------------------------------
// CustomLSTM: B=2048, T=256, I=5, H=50, O=1
//
// R12 = R6 (best: 494us) with ONE change: activations use the hardware
// tanh.approx.f32 instruction (sm_75+): tanh = 1 MUFU; sigmoid(x) =
// 0.5*tanh(0.5x)+0.5 = 1 MUFU + FMA. Replaces __expf+__fdividef chains
// (2 MUFU + div each) -> phase-B MUFU count halves and the per-task serial
// chain shortens ~2x. Everything else identical to R6:
//   grid=296 (2 independent blocks/SM), 200 threads, NB=7/6, weights
//   k-packed f32x2 in registers (1 gate row/thread), 2 barriers/step,
//   c-state in registers, x prefetched one step ahead.
// ---------------------------------------------------------------------------

typedef unsigned long long ull;

constexpr int T    = 256;
constexpr int I    = 5;
constexpr int H    = 50;
constexpr int NTH  = 200;
constexpr int GRID = 296;
constexpr int BIGB = 272;    // blocks [0,272) have NB=7, rest NB=6
constexpr int NBMAX = 7;
constexpr int HROW = 52;     // 208B row stride, 16B multiple
constexpr int XR   = 8;      // x row stride (floats) = 32B

__device__ __forceinline__ ull fma2(ull a, ull b, ull c) {
    ull d;
    asm("fma.rn.f32x2 %0, %1, %2, %3;" : "=l"(d) : "l"(a), "l"(b), "l"(c));
    return d;
}
__device__ __forceinline__ ull pack2(float x, float y) {
    ull r;
    asm("mov.b64 %0, {%1, %2};" : "=l"(r) : "f"(x), "f"(y));
    return r;
}
__device__ __forceinline__ float2 unpack2(ull v) {
    float2 r;
    asm("mov.b64 {%0, %1}, %2;" : "=f"(r.x), "=f"(r.y) : "l"(v));
    return r;
}
__device__ __forceinline__ float tanha(float x) {
    float r;
    asm("tanh.approx.f32 %0, %1;" : "=f"(r) : "f"(x));
    return r;
}
__device__ __forceinline__ float sigf(float x) {
    return fmaf(0.5f, tanha(0.5f * x), 0.5f);
}

__global__ void __launch_bounds__(NTH, 2) lstm_fused_kernel(
    const float* __restrict__ x,
    const float* __restrict__ Wxf, const float* __restrict__ bxf,
    const float* __restrict__ Wxi, const float* __restrict__ bxi,
    const float* __restrict__ Wxc, const float* __restrict__ bxc,
    const float* __restrict__ Wxo, const float* __restrict__ bxo,
    const float* __restrict__ Whf, const float* __restrict__ bhf,
    const float* __restrict__ Whi, const float* __restrict__ bhi,
    const float* __restrict__ Whc, const float* __restrict__ bhc,
    const float* __restrict__ Who, const float* __restrict__ bho,
    const float* __restrict__ bf,  const float* __restrict__ bi,
    const float* __restrict__ bc,  const float* __restrict__ bo,
    const float* __restrict__ Wfc, const float* __restrict__ bfc,
    float* __restrict__ out)
{
    __shared__ __align__(16) float gbS[NBMAX][4 * H];   // gate pre-activations
    __shared__ __align__(16) float hS[NBMAX][HROW];     // h state
    __shared__ __align__(16) float xS[2][NBMAX][XR];    // x double buffer

    const int tid = threadIdx.x;
    const int bid = blockIdx.x;
    const int b0  = (bid < BIGB) ? bid * 7 : BIGB * 7 + (bid - BIGB) * 6;
    const int NB  = (bid < BIGB) ? 7 : 6;

    const int g = tid;          // gate row 0..199
    const int q = g / H;        // 0=f 1=i 2=c 3=o
    const int j = g - q * H;

    // ---- weights for this gate row -> registers (k-packed f32x2)
    const float* whp;
    const float* wxp;
    float bt;
    if (q == 0)      { whp = Whf + j * H; wxp = Wxf + j * I; bt = bxf[j] + bhf[j] + bf[j]; }
    else if (q == 1) { whp = Whi + j * H; wxp = Wxi + j * I; bt = bxi[j] + bhi[j] + bi[j]; }
    else if (q == 2) { whp = Whc + j * H; wxp = Wxc + j * I; bt = bxc[j] + bhc[j] + bc[j]; }
    else             { whp = Who + j * H; wxp = Wxo + j * I; bt = bxo[j] + bho[j] + bo[j]; }

    ull w2[H / 2];
#pragma unroll
    for (int k = 0; k < H / 2; k++) w2[k] = pack2(whp[2 * k], whp[2 * k + 1]);
    const ull wx01 = pack2(wxp[0], wxp[1]);
    const ull wx23 = pack2(wxp[2], wxp[3]);
    const ull wx4c = pack2(wxp[4], 0.0f);

    // ---- init shared
    for (int idx = tid; idx < NBMAX * HROW; idx += NTH) (&hS[0][0])[idx] = 0.0f;
    for (int idx = tid; idx < 2 * NBMAX * XR; idx += NTH) (&xS[0][0][0])[idx] = 0.0f;

    // ---- stage x(t=0)
    const int lb = tid / I, pi = tid - lb * I;   // prefetch coords (tid < NB*I)
    if (tid < NB * I)
        xS[0][lb][pi] = x[(size_t)(b0 + lb) * (T * I) + pi];

    // ---- phase-B task coords: task0 = tid, task1 = tid + 200
    const int ub0 = tid / H,      uj0 = tid - ub0 * H;        // ub0 in 0..3
    const int ub1 = 4 + tid / H,  uj1 = uj0;                  // ub1 in 4..7
    const bool has1 = tid < (NB - 4) * H;                     // 150 or 100
    float c0 = 0.0f, c1 = 0.0f;

    __syncthreads();

#define A_ONE(b_) do {                                                       \
        const float* hp_ = &hS[b_][0];                                       \
        ull ae_ = pack2(bt, 0.0f);                                           \
        ull ao_ = 0ull;                                                      \
        _Pragma("unroll")                                                    \
        for (int c_ = 0; c_ < 12; c_++) {                                    \
            ulonglong2 hv_ = *(const ulonglong2*)(hp_ + 4 * c_);             \
            ae_ = fma2(hv_.x, w2[2 * c_],     ae_);                          \
            ao_ = fma2(hv_.y, w2[2 * c_ + 1], ao_);                          \
        }                                                                    \
        ull h48_ = *(const ull*)(hp_ + 48);                                  \
        ae_ = fma2(h48_, w2[24], ae_);                                       \
        const float* xp_ = &xS[t & 1][b_][0];                                \
        ulonglong2 xv_ = *(const ulonglong2*)xp_;                            \
        ae_ = fma2(xv_.x, wx01, ae_);                                        \
        ao_ = fma2(xv_.y, wx23, ao_);                                        \
        ull x4_ = *(const ull*)(xp_ + 4);                                    \
        ae_ = fma2(x4_, wx4c, ae_);                                          \
        float2 e_ = unpack2(ae_), o_ = unpack2(ao_);                         \
        gbS[b_][g] = (e_.x + o_.x) + (e_.y + o_.y);                          \
    } while (0)

    // =============================== time loop ==============================
    for (int t = 0; t < T; t++) {
        // prefetch x(t+1) (independent LDG, hidden under phase A)
        float pf = 0.0f;
        const bool dof = (tid < NB * I) && (t + 1 < T);
        if (dof) pf = x[(size_t)(b0 + lb) * (T * I) + (t + 1) * I + pi];

        // ---- phase A: gate g for all NB batches
        A_ONE(0); A_ONE(1); A_ONE(2);
        A_ONE(3); A_ONE(4); A_ONE(5);
        if (NB > 6) A_ONE(6);
        __syncthreads();

        if (dof) xS[(t + 1) & 1][lb][pi] = pf;

        // ---- phase B: up to 2 (batch,unit) tasks per thread (tanh.approx)
        {
            float gf0 = gbS[ub0][uj0];
            float gi0 = gbS[ub0][H + uj0];
            float gc0 = gbS[ub0][2 * H + uj0];
            float go0 = gbS[ub0][3 * H + uj0];
            float gf1 = 0.f, gi1 = 0.f, gc1 = 0.f, go1 = 0.f;
            if (has1) {
                gf1 = gbS[ub1][uj1];
                gi1 = gbS[ub1][H + uj1];
                gc1 = gbS[ub1][2 * H + uj1];
                go1 = gbS[ub1][3 * H + uj1];
            }
            c0 = sigf(gf0) * c0 + sigf(gi0) * tanha(gc0);
            hS[ub0][uj0] = sigf(go0) * tanha(c0);
            if (has1) {
                c1 = sigf(gf1) * c1 + sigf(gi1) * tanha(gc1);
                hS[ub1][uj1] = sigf(go1) * tanha(c1);
            }
        }
        __syncthreads();
    }
#undef A_ONE

    // ---- final projection: out[b] = h_T[b] . Wfc + bfc   (O = 1)
    if (tid < NB) {
        const float* hp = &hS[tid][0];
        float s = bfc[0];
#pragma unroll
        for (int k = 0; k < H; k++) s += hp[k] * Wfc[k];
        out[b0 + tid] = s;
    }
}

extern "C" void kernel_launch(void* const* d_in, const int* in_sizes, int n_in,
                              void* d_out, int out_size)
{
    (void)in_sizes; (void)n_in; (void)out_size;
    const float* x   = (const float*)d_in[0];
    const float* Wxf = (const float*)d_in[1];
    const float* bxf = (const float*)d_in[2];
    const float* Wxi = (const float*)d_in[3];
    const float* bxi = (const float*)d_in[4];
    const float* Wxc = (const float*)d_in[5];
    const float* bxc = (const float*)d_in[6];
    const float* Wxo = (const float*)d_in[7];
    const float* bxo = (const float*)d_in[8];
    const float* Whf = (const float*)d_in[9];
    const float* bhf = (const float*)d_in[10];
    const float* Whi = (const float*)d_in[11];
    const float* bhi = (const float*)d_in[12];
    const float* Whc = (const float*)d_in[13];
    const float* bhc = (const float*)d_in[14];
    const float* Who = (const float*)d_in[15];
    const float* bho = (const float*)d_in[16];
    const float* bf  = (const float*)d_in[17];
    const float* bi  = (const float*)d_in[18];
    const float* bc  = (const float*)d_in[19];
    const float* bo  = (const float*)d_in[20];
    const float* Wfc = (const float*)d_in[21];
    const float* bfc = (const float*)d_in[22];
    float* out = (float*)d_out;

    lstm_fused_kernel<<<GRID, NTH>>>(
        x,
        Wxf, bxf, Wxi, bxi, Wxc, bxc, Wxo, bxo,
        Whf, bhf, Whi, bhi, Whc, bhc, Who, bho,
        bf, bi, bc, bo,
        Wfc, bfc,
        out);
}

// round 15
// speedup vs baseline: 1.0616x; 1.0616x over previous
#include <cuda_runtime.h>

// ---------------------------------------------------------------------------
// CustomLSTM: B=2048, T=256, I=5, H=50, O=1
//
// R12 = R6 (best: 494us) with ONE change: activations use the hardware
// tanh.approx.f32 instruction (sm_75+): tanh = 1 MUFU; sigmoid(x) =
// 0.5*tanh(0.5x)+0.5 = 1 MUFU + FMA. Replaces __expf+__fdividef chains
// (2 MUFU + div each) -> phase-B MUFU count halves and the per-task serial
// chain shortens ~2x. Everything else identical to R6:
//   grid=296 (2 independent blocks/SM), 200 threads, NB=7/6, weights
//   k-packed f32x2 in registers (1 gate row/thread), 2 barriers/step,
//   c-state in registers, x prefetched one step ahead.
// ---------------------------------------------------------------------------

typedef unsigned long long ull;

constexpr int T    = 256;
constexpr int I    = 5;
constexpr int H    = 50;
constexpr int NTH  = 200;
constexpr int GRID = 296;
constexpr int BIGB = 272;    // blocks [0,272) have NB=7, rest NB=6
constexpr int NBMAX = 7;
constexpr int HROW = 52;     // 208B row stride, 16B multiple
constexpr int XR   = 8;      // x row stride (floats) = 32B

__device__ __forceinline__ ull fma2(ull a, ull b, ull c) {
    ull d;
    asm("fma.rn.f32x2 %0, %1, %2, %3;" : "=l"(d) : "l"(a), "l"(b), "l"(c));
    return d;
}
__device__ __forceinline__ ull pack2(float x, float y) {
    ull r;
    asm("mov.b64 %0, {%1, %2};" : "=l"(r) : "f"(x), "f"(y));
    return r;
}
__device__ __forceinline__ float2 unpack2(ull v) {
    float2 r;
    asm("mov.b64 {%0, %1}, %2;" : "=f"(r.x), "=f"(r.y) : "l"(v));
    return r;
}
__device__ __forceinline__ float tanha(float x) {
    float r;
    asm("tanh.approx.f32 %0, %1;" : "=f"(r) : "f"(x));
    return r;
}
__device__ __forceinline__ float sigf(float x) {
    return fmaf(0.5f, tanha(0.5f * x), 0.5f);
}

__global__ void __launch_bounds__(NTH, 2) lstm_fused_kernel(
    const float* __restrict__ x,
    const float* __restrict__ Wxf, const float* __restrict__ bxf,
    const float* __restrict__ Wxi, const float* __restrict__ bxi,
    const float* __restrict__ Wxc, const float* __restrict__ bxc,
    const float* __restrict__ Wxo, const float* __restrict__ bxo,
    const float* __restrict__ Whf, const float* __restrict__ bhf,
    const float* __restrict__ Whi, const float* __restrict__ bhi,
    const float* __restrict__ Whc, const float* __restrict__ bhc,
    const float* __restrict__ Who, const float* __restrict__ bho,
    const float* __restrict__ bf,  const float* __restrict__ bi,
    const float* __restrict__ bc,  const float* __restrict__ bo,
    const float* __restrict__ Wfc, const float* __restrict__ bfc,
    float* __restrict__ out)
{
    __shared__ __align__(16) float gbS[NBMAX][4 * H];   // gate pre-activations
    __shared__ __align__(16) float hS[NBMAX][HROW];     // h state
    __shared__ __align__(16) float xS[2][NBMAX][XR];    // x double buffer

    const int tid = threadIdx.x;
    const int bid = blockIdx.x;
    const int b0  = (bid < BIGB) ? bid * 7 : BIGB * 7 + (bid - BIGB) * 6;
    const int NB  = (bid < BIGB) ? 7 : 6;

    const int g = tid;          // gate row 0..199
    const int q = g / H;        // 0=f 1=i 2=c 3=o
    const int j = g - q * H;

    // ---- weights for this gate row -> registers (k-packed f32x2)
    const float* whp;
    const float* wxp;
    float bt;
    if (q == 0)      { whp = Whf + j * H; wxp = Wxf + j * I; bt = bxf[j] + bhf[j] + bf[j]; }
    else if (q == 1) { whp = Whi + j * H; wxp = Wxi + j * I; bt = bxi[j] + bhi[j] + bi[j]; }
    else if (q == 2) { whp = Whc + j * H; wxp = Wxc + j * I; bt = bxc[j] + bhc[j] + bc[j]; }
    else             { whp = Who + j * H; wxp = Wxo + j * I; bt = bxo[j] + bho[j] + bo[j]; }

    ull w2[H / 2];
#pragma unroll
    for (int k = 0; k < H / 2; k++) w2[k] = pack2(whp[2 * k], whp[2 * k + 1]);
    const ull wx01 = pack2(wxp[0], wxp[1]);
    const ull wx23 = pack2(wxp[2], wxp[3]);
    const ull wx4c = pack2(wxp[4], 0.0f);

    // ---- init shared
    for (int idx = tid; idx < NBMAX * HROW; idx += NTH) (&hS[0][0])[idx] = 0.0f;
    for (int idx = tid; idx < 2 * NBMAX * XR; idx += NTH) (&xS[0][0][0])[idx] = 0.0f;

    // ---- stage x(t=0)
    const int lb = tid / I, pi = tid - lb * I;   // prefetch coords (tid < NB*I)
    if (tid < NB * I)
        xS[0][lb][pi] = x[(size_t)(b0 + lb) * (T * I) + pi];

    // ---- phase-B task coords: task0 = tid, task1 = tid + 200
    const int ub0 = tid / H,      uj0 = tid - ub0 * H;        // ub0 in 0..3
    const int ub1 = 4 + tid / H,  uj1 = uj0;                  // ub1 in 4..7
    const bool has1 = tid < (NB - 4) * H;                     // 150 or 100
    float c0 = 0.0f, c1 = 0.0f;

    __syncthreads();

#define A_ONE(b_) do {                                                       \
        const float* hp_ = &hS[b_][0];                                       \
        ull ae_ = pack2(bt, 0.0f);                                           \
        ull ao_ = 0ull;                                                      \
        _Pragma("unroll")                                                    \
        for (int c_ = 0; c_ < 12; c_++) {                                    \
            ulonglong2 hv_ = *(const ulonglong2*)(hp_ + 4 * c_);             \
            ae_ = fma2(hv_.x, w2[2 * c_],     ae_);                          \
            ao_ = fma2(hv_.y, w2[2 * c_ + 1], ao_);                          \
        }                                                                    \
        ull h48_ = *(const ull*)(hp_ + 48);                                  \
        ae_ = fma2(h48_, w2[24], ae_);                                       \
        const float* xp_ = &xS[t & 1][b_][0];                                \
        ulonglong2 xv_ = *(const ulonglong2*)xp_;                            \
        ae_ = fma2(xv_.x, wx01, ae_);                                        \
        ao_ = fma2(xv_.y, wx23, ao_);                                        \
        ull x4_ = *(const ull*)(xp_ + 4);                                    \
        ae_ = fma2(x4_, wx4c, ae_);                                          \
        float2 e_ = unpack2(ae_), o_ = unpack2(ao_);                         \
        gbS[b_][g] = (e_.x + o_.x) + (e_.y + o_.y);                          \
    } while (0)

    // =============================== time loop ==============================
    for (int t = 0; t < T; t++) {
        // prefetch x(t+1) (independent LDG, hidden under phase A)
        float pf = 0.0f;
        const bool dof = (tid < NB * I) && (t + 1 < T);
        if (dof) pf = x[(size_t)(b0 + lb) * (T * I) + (t + 1) * I + pi];

        // ---- phase A: gate g for all NB batches
        A_ONE(0); A_ONE(1); A_ONE(2);
        A_ONE(3); A_ONE(4); A_ONE(5);
        if (NB > 6) A_ONE(6);
        __syncthreads();

        if (dof) xS[(t + 1) & 1][lb][pi] = pf;

        // ---- phase B: up to 2 (batch,unit) tasks per thread (tanh.approx)
        {
            float gf0 = gbS[ub0][uj0];
            float gi0 = gbS[ub0][H + uj0];
            float gc0 = gbS[ub0][2 * H + uj0];
            float go0 = gbS[ub0][3 * H + uj0];
            float gf1 = 0.f, gi1 = 0.f, gc1 = 0.f, go1 = 0.f;
            if (has1) {
                gf1 = gbS[ub1][uj1];
                gi1 = gbS[ub1][H + uj1];
                gc1 = gbS[ub1][2 * H + uj1];
                go1 = gbS[ub1][3 * H + uj1];
            }
            c0 = sigf(gf0) * c0 + sigf(gi0) * tanha(gc0);
            hS[ub0][uj0] = sigf(go0) * tanha(c0);
            if (has1) {
                c1 = sigf(gf1) * c1 + sigf(gi1) * tanha(gc1);
                hS[ub1][uj1] = sigf(go1) * tanha(c1);
            }
        }
        __syncthreads();
    }
#undef A_ONE

    // ---- final projection: out[b] = h_T[b] . Wfc + bfc   (O = 1)
    if (tid < NB) {
        const float* hp = &hS[tid][0];
        float s = bfc[0];
#pragma unroll
        for (int k = 0; k < H; k++) s += hp[k] * Wfc[k];
        out[b0 + tid] = s;
    }
}

extern "C" void kernel_launch(void* const* d_in, const int* in_sizes, int n_in,
                              void* d_out, int out_size)
{
    (void)in_sizes; (void)n_in; (void)out_size;
    const float* x   = (const float*)d_in[0];
    const float* Wxf = (const float*)d_in[1];
    const float* bxf = (const float*)d_in[2];
    const float* Wxi = (const float*)d_in[3];
    const float* bxi = (const float*)d_in[4];
    const float* Wxc = (const float*)d_in[5];
    const float* bxc = (const float*)d_in[6];
    const float* Wxo = (const float*)d_in[7];
    const float* bxo = (const float*)d_in[8];
    const float* Whf = (const float*)d_in[9];
    const float* bhf = (const float*)d_in[10];
    const float* Whi = (const float*)d_in[11];
    const float* bhi = (const float*)d_in[12];
    const float* Whc = (const float*)d_in[13];
    const float* bhc = (const float*)d_in[14];
    const float* Who = (const float*)d_in[15];
    const float* bho = (const float*)d_in[16];
    const float* bf  = (const float*)d_in[17];
    const float* bi  = (const float*)d_in[18];
    const float* bc  = (const float*)d_in[19];
    const float* bo  = (const float*)d_in[20];
    const float* Wfc = (const float*)d_in[21];
    const float* bfc = (const float*)d_in[22];
    float* out = (float*)d_out;

    lstm_fused_kernel<<<GRID, NTH>>>(
        x,
        Wxf, bxf, Wxi, bxi, Wxc, bxc, Wxo, bxo,
        Whf, bhf, Whi, bhi, Whc, bhc, Who, bho,
        bf, bi, bc, bo,
        Wfc, bfc,
        out);
}